// round 13
// baseline (speedup 1.0000x reference)
#include <cuda_runtime.h>
#include <cuda_fp16.h>
#include <math.h>
#include <stdint.h>

#define B_   8
#define L_   4096
#define D_   1024
#define H_   1024
#define LAT_ 256
#define KS_  32
#define TM_  128
#define TN_  128
#define BK_  64
#define NCH  (D_ / BK_)   // 16 chunks
#define NT_  512

#define PXB   144             // pitch bytes (64 halves + 16 pad); 16r mod 128 distinct
#define SZX   18432           // one 128-row tile
#define SZSTG (3 * SZX)       // per stage: X_tgt + X_dec + W = 55296
#define NSTG  3
#define OFF_L2A (NSTG * SZSTG)        // 165888
#define OFF_BIA (OFF_L2A + 512)
#define OFF_ACC (OFF_L2A + 1024)      // 256 floats (2 streams x 128)
#define SMEM_DYN (OFF_L2A + 2048)

__device__ float g_Scorr[B_ * KS_ * H_];
__device__ float g_Sdec [B_ * KS_ * H_];
__device__ float g_hT   [B_ * KS_ * H_];
__device__ float g_y    [B_ * KS_ * H_];
__device__ int   g_starts[B_ * KS_];
__device__ int   g_ends  [B_ * KS_];
__device__ __half g_Wf16[H_ * D_];           // W^T fp16 [n][k]
__device__ __half g_X16[2 * B_ * L_ * D_];   // [stream][b][t][d] fp16 (0=tgt,1=dec)

// ---------- helpers ----------
__device__ __forceinline__ uint32_t smem_u32(const void* p) {
    uint32_t a;
    asm("{ .reg .u64 t; cvta.to.shared.u64 t, %1; cvt.u32.u64 %0, t; }" : "=r"(a) : "l"(p));
    return a;
}
__device__ __forceinline__ void cpa16(uint32_t s, const void* g) {
    unsigned long long gg = (unsigned long long)__cvta_generic_to_global(g);
    asm volatile("cp.async.cg.shared.global [%0], [%1], 16;" :: "r"(s), "l"(gg));
}
__device__ __forceinline__ void ldsm4(uint32_t& r0, uint32_t& r1, uint32_t& r2,
                                      uint32_t& r3, uint32_t a) {
    asm volatile("ldmatrix.sync.aligned.m8n8.x4.shared.b16 {%0,%1,%2,%3}, [%4];"
                 : "=r"(r0), "=r"(r1), "=r"(r2), "=r"(r3) : "r"(a));
}
__device__ __forceinline__ void hmma(float* c, uint32_t a0, uint32_t a1, uint32_t a2,
                                     uint32_t a3, uint32_t b0, uint32_t b1) {
    asm volatile(
        "mma.sync.aligned.m16n8k16.row.col.f32.f16.f16.f32 "
        "{%0,%1,%2,%3}, {%4,%5,%6,%7}, {%8,%9}, {%0,%1,%2,%3};"
        : "+f"(c[0]), "+f"(c[1]), "+f"(c[2]), "+f"(c[3])
        : "r"(a0), "r"(a1), "r"(a2), "r"(a3), "r"(b0), "r"(b1));
}

// ---------- kernel 0: segment bounds ----------
__global__ void k_bounds(const int* __restrict__ mask) {
    int b = blockIdx.x, tid = threadIdx.x;
    const int CH = L_ / 256;
    __shared__ int cnt[256], base[256];
    const int* m = mask + (size_t)b * L_ + tid * CH;
    int c = 0;
#pragma unroll
    for (int i = 0; i < CH; i++) c += (m[i] != 0);
    cnt[tid] = c;
    __syncthreads();
    if (tid == 0) { int s = 0; for (int i = 0; i < 256; i++) { base[i] = s; s += cnt[i]; } }
    __syncthreads();
    int r = base[tid];
#pragma unroll
    for (int i = 0; i < CH; i++)
        if (m[i] != 0) { if (r < KS_) g_ends[b * KS_ + r] = tid * CH + i + 1; r++; }
    __syncthreads();
    if (tid < KS_) g_starts[b * KS_ + tid] = (tid == 0) ? 0 : g_ends[b * KS_ + tid - 1];
}

// ---------- kernel 0b: W transpose + fp16 ----------
__global__ void k_prepW(const float* __restrict__ W) {     // W[k][n] -> g_Wf16[n][k]
    __shared__ float t[32][33];
    int n0 = blockIdx.x * 32, k0 = blockIdx.y * 32;
    for (int i = threadIdx.y; i < 32; i += 8)
        t[i][threadIdx.x] = W[(size_t)(k0 + i) * H_ + n0 + threadIdx.x];
    __syncthreads();
    for (int i = threadIdx.y; i < 32; i += 8)
        g_Wf16[(size_t)(n0 + i) * D_ + (k0 + threadIdx.x)] = __float2half_rn(t[threadIdx.x][i]);
}

// ---------- kernel 0c: X -> fp16 (both streams, one launch) ----------
__global__ void k_prepX2(const float* __restrict__ tgt, const float* __restrict__ dec,
                         __half* __restrict__ dst) {
    const size_t BLD = (size_t)B_ * L_ * D_;
    size_t i = (size_t)(blockIdx.x * blockDim.x + threadIdx.x) * 8;
    const float* src = (i < BLD) ? (tgt + i) : (dec + (i - BLD));
    float4 v0 = *(const float4*)(src);
    float4 v1 = *(const float4*)(src + 4);
    __half2 h[4];
    h[0] = __floats2half2_rn(v0.x, v0.y);
    h[1] = __floats2half2_rn(v0.z, v0.w);
    h[2] = __floats2half2_rn(v1.x, v1.y);
    h[3] = __floats2half2_rn(v1.z, v1.w);
    *(uint4*)(dst + i) = *(uint4*)h;
}

// ---------- kernel 1: dual-stream HMMA fused GEMM + weighted segment reduce ----
// 512 threads: warps 0-7 -> stream 0 (tgt/corr), warps 8-15 -> stream 1 (dec).
// Shared W tile per stage; single-sync 3-stage pipeline, BK=64.
__global__ __launch_bounds__(NT_, 1)
void k_mma(const float* __restrict__ bproj, const float* __restrict__ araw) {
    extern __shared__ char smem[];
    const uint32_t sb = smem_u32(smem);

    const int tid = threadIdx.x, wid = tid >> 5, lane = tid & 31;
    const int sid = wid >> 3;                 // stream of this warp
    const int w8 = wid & 7, wm = w8 >> 2, wn = w8 & 3;
    const int b = blockIdx.z;
    const int kseg = blockIdx.y, ht0 = blockIdx.x * TN_;
    const __half* __restrict__ X0 = g_X16 + (size_t)b * L_ * D_;                    // tgt
    const __half* __restrict__ X1 = g_X16 + ((size_t)B_ + b) * L_ * D_;             // dec
    const int segs = g_starts[b * KS_ + kseg];
    const int sege = g_ends  [b * KS_ + kseg];

    float* l2a_s  = (float*)(smem + OFF_L2A);
    float* bias_s = (float*)(smem + OFF_BIA);
    float* acc_s  = (float*)(smem + OFF_ACC);   // [2][128]
    if (tid < TN_) {
        float a = 1.0f / (1.0f + expf(-araw[ht0 + tid]));
        l2a_s[tid]  = log2f(a);
        bias_s[tid] = bproj[ht0 + tid];
    }
    if (tid < 2 * TN_) acc_s[tid] = 0.0f;

    // loader: lr3 = tid>>3 (0..63), lsg = (tid&7)*16
    // X: q=0..3 -> row256 = lr3+q*64 (0..255); xs=row256>>7 (stream), r=row256&127
    // W: q=0..1 -> row = lr3+q*64 (0..127)
    const int lr3 = tid >> 3, lsg = (tid & 7) * 16;
    // ldmatrix per-lane offsets
    const int lane7 = lane & 7;
    const uint32_t a_off = (uint32_t)(sid * SZX +
                                      (wm * 64 + ((lane >> 3) & 1) * 8 + lane7) * PXB
                                      + ((lane >> 4) & 1) * 16);
    const uint32_t b_off = (uint32_t)(2 * SZX +
                                      (wn * 32 + ((lane >> 4) & 1) * 8 + lane7) * PXB
                                      + ((lane >> 3) & 1) * 16);
    const int lrow = lane >> 2, lk2 = (lane & 3) * 2;

    for (int cs = segs; cs < sege; cs += TM_) {
        float acc[4][4][4];
#pragma unroll
        for (int i = 0; i < 4; i++)
#pragma unroll
            for (int j = 0; j < 4; j++)
#pragma unroll
                for (int q = 0; q < 4; q++) acc[i][j][q] = 0.0f;

        // clamped global rows for the 4 X loader rows
        const __half* xsrc[4];
#pragma unroll
        for (int q = 0; q < 4; q++) {
            int row256 = lr3 + q * 64;
            int r = row256 & 127;
            int gr = (cs + r < L_) ? (cs + r) : (L_ - 1);
            xsrc[q] = ((row256 >> 7) ? X1 : X0) + (size_t)gr * D_;
        }

        // prologue: chunks 0..NSTG-2
#pragma unroll
        for (int s = 0; s < NSTG - 1; s++) {
            const int kt = s * BK_;
            const uint32_t stg = sb + s * SZSTG;
#pragma unroll
            for (int q = 0; q < 4; q++) {
                int row256 = lr3 + q * 64;
                cpa16(stg + (row256 >> 7) * SZX + (row256 & 127) * PXB + lsg,
                      xsrc[q] + kt + lsg / 2);
            }
#pragma unroll
            for (int q = 0; q < 2; q++) {
                const int row = lr3 + q * 64;
                cpa16(stg + 2 * SZX + row * PXB + lsg,
                      g_Wf16 + (size_t)(ht0 + row) * D_ + kt + lsg / 2);
            }
            asm volatile("cp.async.commit_group;");
        }
        asm volatile("cp.async.wait_group %0;" :: "n"(NSTG - 2));
        __syncthreads();

#pragma unroll 1
        for (int c = 0; c < NCH; c++) {
            // ---- compute chunk c (4 k16 steps), dual stream via sid ----
            const uint32_t stg = sb + (c % NSTG) * SZSTG;
#pragma unroll
            for (int ks = 0; ks < 4; ks++) {
                uint32_t b0[4], b1[4];
#pragma unroll
                for (int p = 0; p < 2; p++)
                    ldsm4(b0[2 * p], b1[2 * p], b0[2 * p + 1], b1[2 * p + 1],
                          stg + b_off + p * (16 * PXB) + ks * 32);
#pragma unroll
                for (int mt = 0; mt < 4; mt++) {
                    uint32_t a0, a1, a2, a3;
                    ldsm4(a0, a1, a2, a3, stg + a_off + mt * (16 * PXB) + ks * 32);
#pragma unroll
                    for (int nt = 0; nt < 4; nt++)
                        hmma(acc[mt][nt], a0, a1, a2, a3, b0[nt], b1[nt]);
                }
            }

            // ---- issue loads for chunk c+NSTG-1 into buf (c-1)%NSTG ----
            if (c + NSTG - 1 < NCH) {
                const int kt = (c + NSTG - 1) * BK_;
                const uint32_t stw = sb + ((c + NSTG - 1) % NSTG) * SZSTG;
#pragma unroll
                for (int q = 0; q < 4; q++) {
                    int row256 = lr3 + q * 64;
                    cpa16(stw + (row256 >> 7) * SZX + (row256 & 127) * PXB + lsg,
                          xsrc[q] + kt + lsg / 2);
                }
#pragma unroll
                for (int q = 0; q < 2; q++) {
                    const int row = lr3 + q * 64;
                    cpa16(stw + 2 * SZX + row * PXB + lsg,
                          g_Wf16 + (size_t)(ht0 + row) * D_ + kt + lsg / 2);
                }
            }
            asm volatile("cp.async.commit_group;");   // possibly empty group
            asm volatile("cp.async.wait_group %0;" :: "n"(NSTG - 2));
            __syncthreads();
        }

        // ---- epilogue: weights a^(sege-1-t), bias, reduce over rows ----
        const int pbase = sege - 1 - cs;
#pragma unroll
        for (int nt = 0; nt < 4; nt++) {
            const int col = wn * 32 + nt * 8 + lk2;
            const float la0 = l2a_s[col], la1 = l2a_s[col + 1];
            const float bi0 = bias_s[col], bi1 = bias_s[col + 1];
            float s0 = 0.f, s1 = 0.f;
#pragma unroll
            for (int mt = 0; mt < 4; mt++) {
                const int r0 = wm * 64 + mt * 16 + lrow;
                const int p0 = pbase - r0, p1 = p0 - 8;
                if (p0 >= 0) {
                    s0 += exp2f((float)p0 * la0) * (acc[mt][nt][0] + bi0);
                    s1 += exp2f((float)p0 * la1) * (acc[mt][nt][1] + bi1);
                }
                if (p1 >= 0) {
                    s0 += exp2f((float)p1 * la0) * (acc[mt][nt][2] + bi0);
                    s1 += exp2f((float)p1 * la1) * (acc[mt][nt][3] + bi1);
                }
            }
            s0 += __shfl_xor_sync(0xffffffffu, s0, 4);
            s0 += __shfl_xor_sync(0xffffffffu, s0, 8);
            s0 += __shfl_xor_sync(0xffffffffu, s0, 16);
            s1 += __shfl_xor_sync(0xffffffffu, s1, 4);
            s1 += __shfl_xor_sync(0xffffffffu, s1, 8);
            s1 += __shfl_xor_sync(0xffffffffu, s1, 16);
            if (lane < 4) {
                atomicAdd(&acc_s[sid * TN_ + col], s0);
                atomicAdd(&acc_s[sid * TN_ + col + 1], s1);
            }
        }
        __syncthreads();
    }

    if (tid < 2 * TN_) {
        float* g = (tid >= TN_) ? g_Sdec : g_Scorr;
        g[(size_t)(b * KS_ + kseg) * H_ + ht0 + (tid & (TN_ - 1))] = acc_s[tid];
    }
}

// ---------- kernel 2: K-step prefix scan (MLP-friendly) ----------
__global__ void k_scan(const float* __restrict__ araw) {
    int idx = blockIdx.x * blockDim.x + threadIdx.x;
    if (idx >= B_ * H_) return;
    int b = idx / H_, h = idx % H_;
    float a = 1.0f / (1.0f + expf(-araw[h]));
    float l2a = log2f(a);

    float sd[KS_], sc[KS_];
    int   len[KS_];
#pragma unroll
    for (int k = 0; k < KS_; k++) {
        size_t o = (size_t)(b * KS_ + k) * H_ + h;
        sd[k] = g_Sdec[o];
        sc[k] = g_Scorr[o];
        len[k] = g_ends[b * KS_ + k] - g_starts[b * KS_ + k];
    }
    float hp = 0.0f;
#pragma unroll
    for (int k = 0; k < KS_; k++) {
        float ap = exp2f((float)len[k] * l2a);
        g_hT[(size_t)(b * KS_ + k) * H_ + h] = fmaf(ap, hp, sd[k]);
        hp = fmaf(ap, hp, sc[k]);
    }
}

// ---------- heads ----------
__global__ void k_fill_bias(float* __restrict__ C, const float* __restrict__ bias,
                            int N4, int total4) {
    int i = blockIdx.x * blockDim.x + threadIdx.x;
    if (i >= total4) return;
    ((float4*)C)[i] = ((const float4*)bias)[i % N4];
}

__global__ void k_silu(float* __restrict__ y, int n) {
    int i = blockIdx.x * blockDim.x + threadIdx.x;
    if (i >= n) return;
    float v = y[i];
    y[i] = v / (1.0f + expf(-v));
}

__global__ void k_gemm_splitk(const float* __restrict__ A, const float* __restrict__ Bm,
                              float* __restrict__ C, int M, int N, int Kd, int ksplit) {
    __shared__ float Asm[32][36];
    __shared__ float Bsm[32][64];
    const int n0 = blockIdx.x * 64, m0 = blockIdx.y * 32;
    const int kchunk = Kd / ksplit;
    const int kbeg = blockIdx.z * kchunk, kend = kbeg + kchunk;
    const int tid = threadIdx.x;
    const int r0 = (tid >> 5) * 4, c0 = (tid & 31) * 2;
    float acc[4][2];
#pragma unroll
    for (int i = 0; i < 4; i++) { acc[i][0] = 0.f; acc[i][1] = 0.f; }
    const int lam = tid >> 3, lak = (tid & 7) * 4;
    for (int kt = kbeg; kt < kend; kt += 32) {
        float4 va = *reinterpret_cast<const float4*>(A + (size_t)(m0 + lam) * Kd + kt + lak);
        Asm[lak + 0][lam] = va.x; Asm[lak + 1][lam] = va.y;
        Asm[lak + 2][lam] = va.z; Asm[lak + 3][lam] = va.w;
#pragma unroll
        for (int q = 0; q < 2; q++) {
            int e = tid + q * 256, kk = e >> 4, c4 = (e & 15) * 4;
            *reinterpret_cast<float4*>(&Bsm[kk][c4]) =
                *reinterpret_cast<const float4*>(Bm + (size_t)(kt + kk) * N + n0 + c4);
        }
        __syncthreads();
#pragma unroll
        for (int kk = 0; kk < 32; kk++) {
            float a0 = Asm[kk][r0], a1 = Asm[kk][r0 + 1], a2 = Asm[kk][r0 + 2], a3 = Asm[kk][r0 + 3];
            float b0 = Bsm[kk][c0], b1 = Bsm[kk][c0 + 1];
            acc[0][0] = fmaf(a0, b0, acc[0][0]); acc[0][1] = fmaf(a0, b1, acc[0][1]);
            acc[1][0] = fmaf(a1, b0, acc[1][0]); acc[1][1] = fmaf(a1, b1, acc[1][1]);
            acc[2][0] = fmaf(a2, b0, acc[2][0]); acc[2][1] = fmaf(a2, b1, acc[2][1]);
            acc[3][0] = fmaf(a3, b0, acc[3][0]); acc[3][1] = fmaf(a3, b1, acc[3][1]);
        }
        __syncthreads();
    }
#pragma unroll
    for (int i = 0; i < 4; i++)
#pragma unroll
        for (int j = 0; j < 2; j++)
            atomicAdd(&C[(size_t)(m0 + r0 + i) * N + n0 + c0 + j], acc[i][j]);
}

// ---------- launcher ----------
extern "C" void kernel_launch(void* const* d_in, const int* in_sizes, int n_in,
                              void* d_out, int out_size) {
    (void)in_sizes; (void)n_in; (void)out_size;
    const float* dec  = (const float*)d_in[0];
    const float* tgt  = (const float*)d_in[1];
    const float* Wp   = (const float*)d_in[2];
    const float* bp   = (const float*)d_in[3];
    const float* araw = (const float*)d_in[4];
    const float* Wout = (const float*)d_in[5];
    const float* bout = (const float*)d_in[6];
    const float* Wmu  = (const float*)d_in[7];
    const float* bmu  = (const float*)d_in[8];
    const float* Wlv  = (const float*)d_in[9];
    const float* blv  = (const float*)d_in[10];
    const int*   mask = (const int*)  d_in[11];
    float* out = (float*)d_out;

    void *pHT = nullptr, *pY = nullptr, *pX = nullptr;
    cudaGetSymbolAddress(&pHT, g_hT);
    cudaGetSymbolAddress(&pY,  g_y);
    cudaGetSymbolAddress(&pX,  g_X16);
    float* dY  = (float*)pY;
    float* dHT = (float*)pHT;
    __half* dX = (__half*)pX;
    cudaFuncSetAttribute(k_mma, cudaFuncAttributeMaxDynamicSharedMemorySize, SMEM_DYN);

    const int M = B_ * KS_;   // 256
    const int XN8 = 2 * B_ * L_ * D_ / 8;

    k_bounds<<<B_, 256>>>(mask);
    k_prepW<<<dim3(H_ / 32, D_ / 32), dim3(32, 8)>>>(Wp);
    k_prepX2<<<XN8 / 256, 256>>>(tgt, dec, dX);

    dim3 g1(H_ / TN_, KS_, B_);
    k_mma<<<g1, NT_, SMEM_DYN>>>(bp, araw);
    k_scan<<<(B_ * H_) / 256, 256>>>(araw);

    k_fill_bias<<<(M * H_ / 4 + 255) / 256, 256>>>(dY, bout, H_ / 4, M * H_ / 4);
    k_gemm_splitk<<<dim3(H_ / 64, M / 32, 4), 256>>>(dHT, Wout, dY, M, H_, H_, 4);
    k_silu<<<(M * H_ + 255) / 256, 256>>>(dY, M * H_);

    float* outMu = out;
    float* outLv = out + (size_t)M * LAT_;
    k_fill_bias<<<(M * LAT_ / 4 + 255) / 256, 256>>>(outMu, bmu, LAT_ / 4, M * LAT_ / 4);
    k_fill_bias<<<(M * LAT_ / 4 + 255) / 256, 256>>>(outLv, blv, LAT_ / 4, M * LAT_ / 4);
    k_gemm_splitk<<<dim3(LAT_ / 64, M / 32, 4), 256>>>(dY, Wmu, outMu, M, LAT_, H_, 4);
    k_gemm_splitk<<<dim3(LAT_ / 64, M / 32, 4), 256>>>(dY, Wlv, outLv, M, LAT_, H_, 4);
}

// round 14
// speedup vs baseline: 1.1028x; 1.1028x over previous
#include <cuda_runtime.h>
#include <cuda_fp16.h>
#include <math.h>
#include <stdint.h>

#define B_   8
#define L_   4096
#define D_   1024
#define H_   1024
#define LAT_ 256
#define KS_  32
#define TM_  128
#define TN_  128
#define BK_  64
#define NCH  (D_ / BK_)   // 16 chunks

#define PXB  144          // smem pitch bytes (64 halves + 16 pad)
#define SZST 18432        // 128 rows * 144 B per stage
#define NSTG 3
#define OFF_X   0
#define OFF_W   (NSTG * SZST)            // 55296
#define OFF_L2A (2 * NSTG * SZST)        // 110592
#define OFF_BIA (OFF_L2A + 512)
#define OFF_ACC (OFF_L2A + 1024)
#define SMEM_DYN (OFF_L2A + 1536)

__device__ float g_Scorr[B_ * KS_ * H_];
__device__ float g_Sdec [B_ * KS_ * H_];
__device__ float g_hT   [B_ * KS_ * H_];
__device__ float g_y    [B_ * KS_ * H_];
__device__ int   g_starts[B_ * KS_];
__device__ int   g_ends  [B_ * KS_];
__device__ __half g_Wf16[H_ * D_];           // W^T fp16 [n][k]
__device__ __half g_X16[2 * B_ * L_ * D_];   // [stream][b][t][d] fp16

// ---------- helpers ----------
__device__ __forceinline__ uint32_t smem_u32(const void* p) {
    uint32_t a;
    asm("{ .reg .u64 t; cvta.to.shared.u64 t, %1; cvt.u32.u64 %0, t; }" : "=r"(a) : "l"(p));
    return a;
}
__device__ __forceinline__ void cpa16(uint32_t s, const void* g) {
    unsigned long long gg = (unsigned long long)__cvta_generic_to_global(g);
    asm volatile("cp.async.cg.shared.global [%0], [%1], 16;" :: "r"(s), "l"(gg));
}
__device__ __forceinline__ void ldsm4(uint32_t& r0, uint32_t& r1, uint32_t& r2,
                                      uint32_t& r3, uint32_t a) {
    asm volatile("ldmatrix.sync.aligned.m8n8.x4.shared.b16 {%0,%1,%2,%3}, [%4];"
                 : "=r"(r0), "=r"(r1), "=r"(r2), "=r"(r3) : "r"(a));
}
__device__ __forceinline__ void hmma(float* c, uint32_t a0, uint32_t a1, uint32_t a2,
                                     uint32_t a3, uint32_t b0, uint32_t b1) {
    asm volatile(
        "mma.sync.aligned.m16n8k16.row.col.f32.f16.f16.f32 "
        "{%0,%1,%2,%3}, {%4,%5,%6,%7}, {%8,%9}, {%0,%1,%2,%3};"
        : "+f"(c[0]), "+f"(c[1]), "+f"(c[2]), "+f"(c[3])
        : "r"(a0), "r"(a1), "r"(a2), "r"(a3), "r"(b0), "r"(b1));
}

// ---------- kernel 0: segment bounds ----------
__global__ void k_bounds(const int* __restrict__ mask) {
    int b = blockIdx.x, tid = threadIdx.x;
    const int CH = L_ / 256;
    __shared__ int cnt[256], base[256];
    const int* m = mask + (size_t)b * L_ + tid * CH;
    int c = 0;
#pragma unroll
    for (int i = 0; i < CH; i++) c += (m[i] != 0);
    cnt[tid] = c;
    __syncthreads();
    if (tid == 0) { int s = 0; for (int i = 0; i < 256; i++) { base[i] = s; s += cnt[i]; } }
    __syncthreads();
    int r = base[tid];
#pragma unroll
    for (int i = 0; i < CH; i++)
        if (m[i] != 0) { if (r < KS_) g_ends[b * KS_ + r] = tid * CH + i + 1; r++; }
    __syncthreads();
    if (tid < KS_) g_starts[b * KS_ + tid] = (tid == 0) ? 0 : g_ends[b * KS_ + tid - 1];
}

// ---------- kernel 0b: W transpose + fp16 ----------
__global__ void k_prepW(const float* __restrict__ W) {     // W[k][n] -> g_Wf16[n][k]
    __shared__ float t[32][33];
    int n0 = blockIdx.x * 32, k0 = blockIdx.y * 32;
    for (int i = threadIdx.y; i < 32; i += 8)
        t[i][threadIdx.x] = W[(size_t)(k0 + i) * H_ + n0 + threadIdx.x];
    __syncthreads();
    for (int i = threadIdx.y; i < 32; i += 8)
        g_Wf16[(size_t)(n0 + i) * D_ + (k0 + threadIdx.x)] = __float2half_rn(t[threadIdx.x][i]);
}

// ---------- kernel 0c: X -> fp16, both streams ----------
__global__ void k_prepX2(const float* __restrict__ tgt, const float* __restrict__ dec,
                         __half* __restrict__ dst) {
    const size_t BLD = (size_t)B_ * L_ * D_;
    size_t i = (size_t)(blockIdx.x * blockDim.x + threadIdx.x) * 8;
    const float* src = (i < BLD) ? (tgt + i) : (dec + (i - BLD));
    float4 v0 = *(const float4*)(src);
    float4 v1 = *(const float4*)(src + 4);
    __half2 h[4];
    h[0] = __floats2half2_rn(v0.x, v0.y);
    h[1] = __floats2half2_rn(v0.z, v0.w);
    h[2] = __floats2half2_rn(v1.x, v1.y);
    h[3] = __floats2half2_rn(v1.z, v1.w);
    *(uint4*)(dst + i) = *(uint4*)h;
}

// ---------- kernel 1: HMMA fused GEMM + weighted segment reduce (R12 config) ---
__global__ __launch_bounds__(256, 2)
void k_mma(const float* __restrict__ bproj, const float* __restrict__ araw) {
    extern __shared__ char smem[];
    const uint32_t sb = smem_u32(smem);

    const int tid = threadIdx.x, wid = tid >> 5, lane = tid & 31;
    const int wm = wid >> 2, wn = wid & 3;
    const int z = blockIdx.z, b = z >> 1, stream = z & 1;
    const int kseg = blockIdx.y, ht0 = blockIdx.x * TN_;
    const __half* __restrict__ Xb =
        g_X16 + ((size_t)stream * B_ + b) * L_ * D_;
    const int segs = g_starts[b * KS_ + kseg];
    const int sege = g_ends  [b * KS_ + kseg];

    float* l2a_s  = (float*)(smem + OFF_L2A);
    float* bias_s = (float*)(smem + OFF_BIA);
    float* acc_s  = (float*)(smem + OFF_ACC);
    if (tid < TN_) {
        float a = 1.0f / (1.0f + expf(-araw[ht0 + tid]));
        l2a_s[tid]  = log2f(a);
        bias_s[tid] = bproj[ht0 + tid];
        acc_s[tid]  = 0.0f;
    }

    const int lr0 = tid >> 3;            // base row (0..31), +q*32
    const int lsg = (tid & 7) * 16;
    const int lane7 = lane & 7;
    const uint32_t a_off = (uint32_t)((wm * 64 + ((lane >> 3) & 1) * 8 + lane7) * PXB
                                      + ((lane >> 4) & 1) * 16);
    const uint32_t b_off = (uint32_t)((wn * 32 + ((lane >> 4) & 1) * 8 + lane7) * PXB
                                      + ((lane >> 3) & 1) * 16);
    const int lrow = lane >> 2, lk2 = (lane & 3) * 2;

    for (int cs = segs; cs < sege; cs += TM_) {
        float acc[4][4][4];
#pragma unroll
        for (int i = 0; i < 4; i++)
#pragma unroll
            for (int j = 0; j < 4; j++)
#pragma unroll
                for (int q = 0; q < 4; q++) acc[i][j][q] = 0.0f;

        int xr[4];
#pragma unroll
        for (int q = 0; q < 4; q++) {
            int r = cs + lr0 + q * 32;
            xr[q] = (r < L_) ? r : (L_ - 1);
        }

#pragma unroll
        for (int s = 0; s < NSTG - 1; s++) {
            const int kt = s * BK_;
#pragma unroll
            for (int q = 0; q < 4; q++) {
                const int row = lr0 + q * 32;
                cpa16(sb + OFF_X + s * SZST + row * PXB + lsg,
                      Xb + (size_t)xr[q] * D_ + kt + lsg / 2);
                cpa16(sb + OFF_W + s * SZST + row * PXB + lsg,
                      g_Wf16 + (size_t)(ht0 + row) * D_ + kt + lsg / 2);
            }
            asm volatile("cp.async.commit_group;");
        }
        asm volatile("cp.async.wait_group %0;" :: "n"(NSTG - 2));
        __syncthreads();

#pragma unroll 1
        for (int c = 0; c < NCH; c++) {
            const int cur = c % NSTG;
            const uint32_t xh = sb + OFF_X + cur * SZST;
            const uint32_t wb = sb + OFF_W + cur * SZST;
#pragma unroll
            for (int ks = 0; ks < 4; ks++) {
                uint32_t b0[4], b1[4];
#pragma unroll
                for (int p = 0; p < 2; p++)
                    ldsm4(b0[2 * p], b1[2 * p], b0[2 * p + 1], b1[2 * p + 1],
                          wb + b_off + p * (16 * PXB) + ks * 32);
#pragma unroll
                for (int mt = 0; mt < 4; mt++) {
                    uint32_t a0, a1, a2, a3;
                    ldsm4(a0, a1, a2, a3, xh + a_off + mt * (16 * PXB) + ks * 32);
#pragma unroll
                    for (int nt = 0; nt < 4; nt++)
                        hmma(acc[mt][nt], a0, a1, a2, a3, b0[nt], b1[nt]);
                }
            }

            if (c + NSTG - 1 < NCH) {
                const int kt = (c + NSTG - 1) * BK_;
                const int st = (c + NSTG - 1) % NSTG;
#pragma unroll
                for (int q = 0; q < 4; q++) {
                    const int row = lr0 + q * 32;
                    cpa16(sb + OFF_X + st * SZST + row * PXB + lsg,
                          Xb + (size_t)xr[q] * D_ + kt + lsg / 2);
                    cpa16(sb + OFF_W + st * SZST + row * PXB + lsg,
                          g_Wf16 + (size_t)(ht0 + row) * D_ + kt + lsg / 2);
                }
            }
            asm volatile("cp.async.commit_group;");
            asm volatile("cp.async.wait_group %0;" :: "n"(NSTG - 2));
            __syncthreads();
        }

        const int pbase = sege - 1 - cs;
#pragma unroll
        for (int nt = 0; nt < 4; nt++) {
            const int col = wn * 32 + nt * 8 + lk2;
            const float la0 = l2a_s[col], la1 = l2a_s[col + 1];
            const float bi0 = bias_s[col], bi1 = bias_s[col + 1];
            float s0 = 0.f, s1 = 0.f;
#pragma unroll
            for (int mt = 0; mt < 4; mt++) {
                const int r0 = wm * 64 + mt * 16 + lrow;
                const int p0 = pbase - r0, p1 = p0 - 8;
                if (p0 >= 0) {
                    s0 += exp2f((float)p0 * la0) * (acc[mt][nt][0] + bi0);
                    s1 += exp2f((float)p0 * la1) * (acc[mt][nt][1] + bi1);
                }
                if (p1 >= 0) {
                    s0 += exp2f((float)p1 * la0) * (acc[mt][nt][2] + bi0);
                    s1 += exp2f((float)p1 * la1) * (acc[mt][nt][3] + bi1);
                }
            }
            s0 += __shfl_xor_sync(0xffffffffu, s0, 4);
            s0 += __shfl_xor_sync(0xffffffffu, s0, 8);
            s0 += __shfl_xor_sync(0xffffffffu, s0, 16);
            s1 += __shfl_xor_sync(0xffffffffu, s1, 4);
            s1 += __shfl_xor_sync(0xffffffffu, s1, 8);
            s1 += __shfl_xor_sync(0xffffffffu, s1, 16);
            if (lane < 4) {
                atomicAdd(&acc_s[col], s0);
                atomicAdd(&acc_s[col + 1], s1);
            }
        }
        __syncthreads();
    }

    float* g = stream ? g_Sdec : g_Scorr;
    if (tid < TN_)
        g[(size_t)(b * KS_ + kseg) * H_ + ht0 + tid] = acc_s[tid];
}

// ---------- kernel 2: K-step prefix scan (MLP-friendly) ----------
__global__ void k_scan(const float* __restrict__ araw) {
    int idx = blockIdx.x * blockDim.x + threadIdx.x;
    if (idx >= B_ * H_) return;
    int b = idx / H_, h = idx % H_;
    float a = 1.0f / (1.0f + expf(-araw[h]));
    float l2a = log2f(a);

    float sd[KS_], sc[KS_];
    int   len[KS_];
#pragma unroll
    for (int k = 0; k < KS_; k++) {
        size_t o = (size_t)(b * KS_ + k) * H_ + h;
        sd[k] = g_Sdec[o];
        sc[k] = g_Scorr[o];
        len[k] = g_ends[b * KS_ + k] - g_starts[b * KS_ + k];
    }
    float hp = 0.0f;
#pragma unroll
    for (int k = 0; k < KS_; k++) {
        float ap = exp2f((float)len[k] * l2a);
        g_hT[(size_t)(b * KS_ + k) * H_ + h] = fmaf(ap, hp, sd[k]);
        hp = fmaf(ap, hp, sc[k]);
    }
}

// ---------- heads ----------
// one kernel fills all three outputs with their biases
__global__ void k_fill3(float* __restrict__ y, const float* __restrict__ bout,
                        float* __restrict__ mu, const float* __restrict__ bmu,
                        float* __restrict__ lv, const float* __restrict__ blv) {
    const int NY = B_ * KS_ * H_ / 4;     // 65536
    const int NM = B_ * KS_ * LAT_ / 4;   // 16384
    int i = blockIdx.x * blockDim.x + threadIdx.x;
    if (i < NY) { ((float4*)y)[i] = ((const float4*)bout)[i % (H_ / 4)]; return; }
    i -= NY;
    if (i < NM) { ((float4*)mu)[i] = ((const float4*)bmu)[i % (LAT_ / 4)]; return; }
    i -= NM;
    if (i < NM) ((float4*)lv)[i] = ((const float4*)blv)[i % (LAT_ / 4)];
}

__global__ void k_silu(float* __restrict__ y, int n) {
    int i = blockIdx.x * blockDim.x + threadIdx.x;
    if (i >= n) return;
    float v = y[i];
    y[i] = v / (1.0f + expf(-v));
}

__global__ void k_gemm_splitk(const float* __restrict__ A, const float* __restrict__ Bm,
                              float* __restrict__ C, int M, int N, int Kd, int ksplit) {
    __shared__ float Asm[32][36];
    __shared__ float Bsm[32][64];
    const int n0 = blockIdx.x * 64, m0 = blockIdx.y * 32;
    const int kchunk = Kd / ksplit;
    const int kbeg = blockIdx.z * kchunk, kend = kbeg + kchunk;
    const int tid = threadIdx.x;
    const int r0 = (tid >> 5) * 4, c0 = (tid & 31) * 2;
    float acc[4][2];
#pragma unroll
    for (int i = 0; i < 4; i++) { acc[i][0] = 0.f; acc[i][1] = 0.f; }
    const int lam = tid >> 3, lak = (tid & 7) * 4;
    for (int kt = kbeg; kt < kend; kt += 32) {
        float4 va = *reinterpret_cast<const float4*>(A + (size_t)(m0 + lam) * Kd + kt + lak);
        Asm[lak + 0][lam] = va.x; Asm[lak + 1][lam] = va.y;
        Asm[lak + 2][lam] = va.z; Asm[lak + 3][lam] = va.w;
#pragma unroll
        for (int q = 0; q < 2; q++) {
            int e = tid + q * 256, kk = e >> 4, c4 = (e & 15) * 4;
            *reinterpret_cast<float4*>(&Bsm[kk][c4]) =
                *reinterpret_cast<const float4*>(Bm + (size_t)(kt + kk) * N + n0 + c4);
        }
        __syncthreads();
#pragma unroll
        for (int kk = 0; kk < 32; kk++) {
            float a0 = Asm[kk][r0], a1 = Asm[kk][r0 + 1], a2 = Asm[kk][r0 + 2], a3 = Asm[kk][r0 + 3];
            float b0 = Bsm[kk][c0], b1 = Bsm[kk][c0 + 1];
            acc[0][0] = fmaf(a0, b0, acc[0][0]); acc[0][1] = fmaf(a0, b1, acc[0][1]);
            acc[1][0] = fmaf(a1, b0, acc[1][0]); acc[1][1] = fmaf(a1, b1, acc[1][1]);
            acc[2][0] = fmaf(a2, b0, acc[2][0]); acc[2][1] = fmaf(a2, b1, acc[2][1]);
            acc[3][0] = fmaf(a3, b0, acc[3][0]); acc[3][1] = fmaf(a3, b1, acc[3][1]);
        }
        __syncthreads();
    }
#pragma unroll
    for (int i = 0; i < 4; i++)
#pragma unroll
        for (int j = 0; j < 2; j++)
            atomicAdd(&C[(size_t)(m0 + r0 + i) * N + n0 + c0 + j], acc[i][j]);
}

// mu and lv in one launch: blockIdx.z = head * ksplit + kchunk_idx
__global__ void k_gemm_ml(const float* __restrict__ A,
                          const float* __restrict__ Wmu, const float* __restrict__ Wlv,
                          float* __restrict__ mu, float* __restrict__ lv,
                          int M, int N, int Kd, int ksplit) {
    const int head = blockIdx.z / ksplit;
    const int kz   = blockIdx.z % ksplit;
    const float* Bm = head ? Wlv : Wmu;
    float* C        = head ? lv  : mu;

    __shared__ float Asm[32][36];
    __shared__ float Bsm[32][64];
    const int n0 = blockIdx.x * 64, m0 = blockIdx.y * 32;
    const int kchunk = Kd / ksplit;
    const int kbeg = kz * kchunk, kend = kbeg + kchunk;
    const int tid = threadIdx.x;
    const int r0 = (tid >> 5) * 4, c0 = (tid & 31) * 2;
    float acc[4][2];
#pragma unroll
    for (int i = 0; i < 4; i++) { acc[i][0] = 0.f; acc[i][1] = 0.f; }
    const int lam = tid >> 3, lak = (tid & 7) * 4;
    for (int kt = kbeg; kt < kend; kt += 32) {
        float4 va = *reinterpret_cast<const float4*>(A + (size_t)(m0 + lam) * Kd + kt + lak);
        Asm[lak + 0][lam] = va.x; Asm[lak + 1][lam] = va.y;
        Asm[lak + 2][lam] = va.z; Asm[lak + 3][lam] = va.w;
#pragma unroll
        for (int q = 0; q < 2; q++) {
            int e = tid + q * 256, kk = e >> 4, c4 = (e & 15) * 4;
            *reinterpret_cast<float4*>(&Bsm[kk][c4]) =
                *reinterpret_cast<const float4*>(Bm + (size_t)(kt + kk) * N + n0 + c4);
        }
        __syncthreads();
#pragma unroll
        for (int kk = 0; kk < 32; kk++) {
            float a0 = Asm[kk][r0], a1 = Asm[kk][r0 + 1], a2 = Asm[kk][r0 + 2], a3 = Asm[kk][r0 + 3];
            float b0 = Bsm[kk][c0], b1 = Bsm[kk][c0 + 1];
            acc[0][0] = fmaf(a0, b0, acc[0][0]); acc[0][1] = fmaf(a0, b1, acc[0][1]);
            acc[1][0] = fmaf(a1, b0, acc[1][0]); acc[1][1] = fmaf(a1, b1, acc[1][1]);
            acc[2][0] = fmaf(a2, b0, acc[2][0]); acc[2][1] = fmaf(a2, b1, acc[2][1]);
            acc[3][0] = fmaf(a3, b0, acc[3][0]); acc[3][1] = fmaf(a3, b1, acc[3][1]);
        }
        __syncthreads();
    }
#pragma unroll
    for (int i = 0; i < 4; i++)
#pragma unroll
        for (int j = 0; j < 2; j++)
            atomicAdd(&C[(size_t)(m0 + r0 + i) * N + n0 + c0 + j], acc[i][j]);
}

// ---------- launcher ----------
extern "C" void kernel_launch(void* const* d_in, const int* in_sizes, int n_in,
                              void* d_out, int out_size) {
    (void)in_sizes; (void)n_in; (void)out_size;
    const float* dec  = (const float*)d_in[0];
    const float* tgt  = (const float*)d_in[1];
    const float* Wp   = (const float*)d_in[2];
    const float* bp   = (const float*)d_in[3];
    const float* araw = (const float*)d_in[4];
    const float* Wout = (const float*)d_in[5];
    const float* bout = (const float*)d_in[6];
    const float* Wmu  = (const float*)d_in[7];
    const float* bmu  = (const float*)d_in[8];
    const float* Wlv  = (const float*)d_in[9];
    const float* blv  = (const float*)d_in[10];
    const int*   mask = (const int*)  d_in[11];
    float* out = (float*)d_out;

    void *pHT = nullptr, *pY = nullptr, *pX = nullptr;
    cudaGetSymbolAddress(&pHT, g_hT);
    cudaGetSymbolAddress(&pY,  g_y);
    cudaGetSymbolAddress(&pX,  g_X16);
    float* dY  = (float*)pY;
    float* dHT = (float*)pHT;
    __half* dX = (__half*)pX;
    cudaFuncSetAttribute(k_mma, cudaFuncAttributeMaxDynamicSharedMemorySize, SMEM_DYN);

    const int M = B_ * KS_;   // 256
    const int XN8 = 2 * B_ * L_ * D_ / 8;
    float* outMu = out;
    float* outLv = out + (size_t)M * LAT_;

    k_bounds<<<B_, 256>>>(mask);
    k_prepW<<<dim3(H_ / 32, D_ / 32), dim3(32, 8)>>>(Wp);
    k_prepX2<<<XN8 / 256, 256>>>(tgt, dec, dX);

    dim3 g1(H_ / TN_, KS_, B_ * 2);
    k_mma<<<g1, 256, SMEM_DYN>>>(bp, araw);
    k_scan<<<(B_ * H_) / 256, 256>>>(araw);

    // bias-fill all three outputs at once
    const int NF = (M * H_ + 2 * M * LAT_) / 4;   // 98304 float4s
    k_fill3<<<(NF + 255) / 256, 256>>>(dY, bout, outMu, bmu, outLv, blv);

    // y = silu(hT @ W_out + b_out), split-K 8
    k_gemm_splitk<<<dim3(H_ / 64, M / 32, 8), 256>>>(dHT, Wout, dY, M, H_, H_, 8);
    k_silu<<<(M * H_ + 255) / 256, 256>>>(dY, M * H_);

    // mu and logvar in one launch, split-K 4 each
    k_gemm_ml<<<dim3(LAT_ / 64, M / 32, 2 * 4), 256>>>(
        dY, Wmu, Wlv, outMu, outLv, M, LAT_, H_, 4);
}